// round 14
// baseline (speedup 1.0000x reference)
#include <cuda_runtime.h>

#define NN 10000
#define EE 160000
#define EPS 1e-5f
#define ELLW 64
#define CEILDIV(a,b) (((a)+(b)-1)/(b))

// ---------------- scratch (static device globals; no allocation) ----------------
__device__ __align__(16) float g_deg[NN];
__device__ __align__(16) int   g_cnt[NN];
__device__ __align__(16) int   g_ell_src[NN * ELLW];
__device__ __align__(16) float g_ell_w[NN * ELLW];
__device__ __align__(16) float g_y1[NN * 512];
__device__ __align__(16) float g_t1[NN * 512];
__device__ __align__(16) float g_y2[NN * 256];
__device__ __align__(16) float g_p2[NN * 256];
__device__ __align__(16) float g_tx2[NN * 256];
__device__ __align__(16) float g_y3[NN * 128];
__device__ __align__(16) float g_tB1[768 * 512];    // tf32-preconverted weights (K-concat)
__device__ __align__(16) float g_tB2[1024 * 256];
__device__ __align__(16) float g_tB3[768 * 128];
__device__ __align__(16) float g_sums[896];
__device__ __align__(16) float g_ssqs[896];
__device__ __align__(16) float g_bnsc[896];
__device__ __align__(16) float g_bnsh[896];

__device__ __forceinline__ float* buf(int id) {
    switch (id) {
        case 1: return g_y1;
        case 2: return g_t1;
        case 3: return g_y2;
        case 4: return g_p2;
        case 5: return g_tx2;
        case 6: return g_y3;
        case 7: return g_tB1;
        case 8: return g_tB2;
        case 9: return g_tB3;
    }
    return nullptr;
}

__device__ __forceinline__ unsigned f2tf(float x) {
    unsigned u;
    asm("cvt.rna.tf32.f32 %0, %1;" : "=r"(u) : "f"(x));
    return u;
}
__device__ __forceinline__ unsigned fui(float x) { return __float_as_uint(x); }

// ---------------- graph build (ELL by dst) ----------------
__global__ void k_init_graph() {
    int i = blockIdx.x * blockDim.x + threadIdx.x;
    if (i < NN) { g_deg[i] = 0.0f; g_cnt[i] = 0; }
    if (i < 896) { g_sums[i] = 0.0f; g_ssqs[i] = 0.0f; }
}
__global__ void k_deg(const int* __restrict__ ei, const float* __restrict__ ea) {
    int e = blockIdx.x * blockDim.x + threadIdx.x;
    if (e >= EE) return;
    atomicAdd(&g_deg[ei[e]], ea[e]);
}
__global__ void k_norm_push(const int* __restrict__ ei, const float* __restrict__ ea) {
    int e = blockIdx.x * blockDim.x + threadIdx.x;
    if (e >= EE) return;
    int s = ei[e];
    int d = ei[EE + e];
    float ds = g_deg[s], dd = g_deg[d];
    float is = (ds > 0.0f) ? rsqrtf(ds) : 0.0f;
    float id = (dd > 0.0f) ? rsqrtf(dd) : 0.0f;
    float w = -is * ea[e] * id;
    int pos = atomicAdd(&g_cnt[d], 1);
    g_ell_src[d * ELLW + pos] = s;
    g_ell_w[d * ELLW + pos] = w;
}

// ---------------- BN coefficients ----------------
__global__ void k_bn_coef(const float* __restrict__ gamma, const float* __restrict__ beta,
                          int n, int F, int soff) {
    int f = threadIdx.x;
    if (f >= F) return;
    float inv_n = 1.0f / (float)n;
    float mu = g_sums[soff + f] * inv_n;
    float var = g_ssqs[soff + f] * inv_n - mu * mu;
    float sc = gamma[f] * rsqrtf(var + EPS);
    g_bnsc[soff + f] = sc;
    g_bnsh[soff + f] = beta[f] - mu * sc;
}

// ---------------- one-time B tf32 pre-convert (+K-concat) ----------------
__global__ void k_cvtB(const float* __restrict__ B0, const float* __restrict__ B1,
                       const float* __restrict__ B2, int Kseg, int N, int K, int dstid) {
    int idx = blockIdx.x * blockDim.x + threadIdx.x;
    if (idx >= K * N) return;
    int row = idx / N;
    int col = idx - row * N;
    int seg = row / Kseg;
    int rloc = row - seg * Kseg;
    const float* B = (seg == 0) ? B0 : (seg == 1) ? B1 : B2;
    buf(dstid)[idx] = __uint_as_float(f2tf(B[rloc * N + col]));
}

// ---------------- tf32 GEMM: BM=64, BN=128, BKT=16; fragment-major A smem,
// B in XOR-permuted fragment pages (LDS.128 both sides), preconverted B ----------------
#define BMT 64
#define BNT 128
#define BKT 16
#define NF 4
#define A_STAGE (2 * NF * 128)   // 1024 floats
#define B_STAGE (BKT * 128)      // 2048 floats: [k][g][qr'][j]

__global__ __launch_bounds__(256, 3) void gemm_tf32(
    const float* __restrict__ Aext, int aid0, int aid1, int aid2, int tBid,
    const float* __restrict__ bias, int Cid,
    int M, int N, int Kseg, int segs, int soff, int coff0)
{
    __shared__ __align__(16) float As[2][A_STAGE];
    __shared__ __align__(16) float Bs[2][B_STAGE];

    const float* Ap[3];
    Ap[0] = Aext ? Aext : buf(aid0);
    Ap[1] = buf(aid1);
    Ap[2] = buf(aid2);
    float* C = buf(Cid);

    const int tid = threadIdx.x;
    const int lane = tid & 31;
    const int warp = tid >> 5;
    const int qr = lane >> 2;
    const int qc = lane & 3;
    const int wm = (warp & 1) * 32;
    const int ms0 = (warp & 1) * 2;
    const int wn = (warp >> 1) * 32;

    const int row0 = blockIdx.y * BMT;
    const int col0 = blockIdx.x * BNT;

    // A loader: one float4 per thread: row=tid/4, k=(tid&3)*4
    const int arow = tid >> 2;
    const int ak = (tid & 3) << 2;
    const bool avalid = (row0 + arow) < M;
    const int wr = arow & 15;
    const int wms = arow >> 4;
    const int wkh = ak >> 3;
    const int wkb = (ak >> 2) & 1;
    const int xsw = ((wr >> 1) & 3) << 2;
    const int awbase = (wkh * NF + wms) * 128 + ((wr & 7) << 4) + (wr >> 3) + (wkb << 1);

    // A fragment read base
    const int rpos = (qr << 2) + (qc ^ ((qr >> 1) & 3));
    const int ardbase = ms0 * 128 + (rpos << 2);

    // B loader: rows brow / brow+8, cols bcol..bcol+3 -> [k][g][qr'][j], qr'=qr^2(k&3)^g
    const int brow = tid >> 5;
    const int bcol = (tid & 31) << 2;
    const int c3 = brow & 3;              // (brow+8)&3 is identical
    int bwoff[4];
#pragma unroll
    for (int e = 0; e < 4; e++) {
        int n = bcol + e;
        int gg = (n >> 5) & 3;
        int jj = (n >> 3) & 3;
        int q = n & 7;
        int qp = q ^ (2 * c3) ^ gg;
        bwoff[e] = brow * 128 + gg * 32 + qp * 4 + jj;
    }

    // B fragment read base: per kh, row k=kh*8+qc (k&3=qc), qr'=qr^2qc^gr
    const int gr = warp >> 1;
    const int qrp = qr ^ (2 * qc) ^ gr;
    const int brd0 = qc * 128 + gr * 32 + qrp * 4;   // kh adds 1024, reg1 adds 512

    float acc[2][4][4];
#pragma unroll
    for (int i = 0; i < 2; i++)
#pragma unroll
        for (int j = 0; j < 4; j++)
#pragma unroll
            for (int e = 0; e < 4; e++) acc[i][j][e] = 0.0f;

    // pointer-walk state (no division in main loop)
    const size_t aoff = (size_t)(row0 + arow) * Kseg + ak;
    const float* pA = Ap[0] + aoff;
    const float* psc = g_bnsc + (coff0 >= 0 ? coff0 : 0) + ak;
    const float* psh = g_bnsh + (coff0 >= 0 ? coff0 : 0) + ak;
    const float* pB = buf(tBid) + (size_t)brow * N + col0 + bcol;
    const int bstep = BKT * N;
    int segi = 0, kcnt = 0;
    const int kperseg = Kseg / BKT;
    const int niter = kperseg * segs;

    float4 rA, rB[2];
    auto fetch = [&]() {
        rA = make_float4(0.f, 0.f, 0.f, 0.f);
        if (avalid) rA = *(const float4*)pA;
        if (coff0 >= 0 && segi == 0) {
            float4 sc = *(const float4*)psc;
            float4 sh = *(const float4*)psh;
            rA.x = fmaxf(fmaf(rA.x, sc.x, sh.x), 0.f);
            rA.y = fmaxf(fmaf(rA.y, sc.y, sh.y), 0.f);
            rA.z = fmaxf(fmaf(rA.z, sc.z, sh.z), 0.f);
            rA.w = fmaxf(fmaf(rA.w, sc.w, sh.w), 0.f);
        }
        rB[0] = *(const float4*)pB;
        rB[1] = *(const float4*)(pB + (size_t)8 * N);
    };
    auto advance = [&]() {
        kcnt++;
        if (kcnt == kperseg) {
            kcnt = 0; segi++;
            if (segi < segs) pA = Ap[segi] + aoff;
        } else {
            pA += BKT;
        }
        psc += BKT; psh += BKT;
        pB += bstep;
    };
    auto commit = [&](int s) {
        float* Aw = As[s];
        Aw[awbase + ((0 << 2) ^ xsw)] = __uint_as_float(f2tf(rA.x));
        Aw[awbase + ((1 << 2) ^ xsw)] = __uint_as_float(f2tf(rA.y));
        Aw[awbase + ((2 << 2) ^ xsw)] = __uint_as_float(f2tf(rA.z));
        Aw[awbase + ((3 << 2) ^ xsw)] = __uint_as_float(f2tf(rA.w));
        float* Bw = Bs[s];
        Bw[bwoff[0]] = rB[0].x;
        Bw[bwoff[1]] = rB[0].y;
        Bw[bwoff[2]] = rB[0].z;
        Bw[bwoff[3]] = rB[0].w;
        Bw[bwoff[0] + 1024] = rB[1].x;
        Bw[bwoff[1] + 1024] = rB[1].y;
        Bw[bwoff[2] + 1024] = rB[1].z;
        Bw[bwoff[3] + 1024] = rB[1].w;
    };

    fetch();
    advance();
    commit(0);
    __syncthreads();

    int cur = 0;
    for (int it = 0; it < niter; it++, cur ^= 1) {
        const bool hasNext = (it + 1) < niter;
        if (hasNext) { fetch(); advance(); }

        const float* Ac = As[cur];
        const float* Bc = Bs[cur];
#pragma unroll
        for (int kh = 0; kh < 2; kh++) {
            const float* Af = Ac + kh * (NF * 128) + ardbase;
            float4 fa0 = *(const float4*)(Af);
            float4 fa1 = *(const float4*)(Af + 128);
            const float* Bf = Bc + kh * 1024 + brd0;
            float4 q0 = *(const float4*)(Bf);          // b0: j=0..3
            float4 q1 = *(const float4*)(Bf + 512);    // b1: j=0..3
            const unsigned b0a[4] = {fui(q0.x), fui(q0.y), fui(q0.z), fui(q0.w)};
            const unsigned b1a[4] = {fui(q1.x), fui(q1.y), fui(q1.z), fui(q1.w)};
#pragma unroll
            for (int j = 0; j < 4; j++) {
                asm volatile(
                    "mma.sync.aligned.m16n8k8.row.col.f32.tf32.tf32.f32 "
                    "{%0,%1,%2,%3}, {%4,%5,%6,%7}, {%8,%9}, {%0,%1,%2,%3};"
                    : "+f"(acc[0][j][0]), "+f"(acc[0][j][1]),
                      "+f"(acc[0][j][2]), "+f"(acc[0][j][3])
                    : "r"(fui(fa0.x)), "r"(fui(fa0.y)), "r"(fui(fa0.z)), "r"(fui(fa0.w)),
                      "r"(b0a[j]), "r"(b1a[j]));
                asm volatile(
                    "mma.sync.aligned.m16n8k8.row.col.f32.tf32.tf32.f32 "
                    "{%0,%1,%2,%3}, {%4,%5,%6,%7}, {%8,%9}, {%0,%1,%2,%3};"
                    : "+f"(acc[1][j][0]), "+f"(acc[1][j][1]),
                      "+f"(acc[1][j][2]), "+f"(acc[1][j][3])
                    : "r"(fui(fa1.x)), "r"(fui(fa1.y)), "r"(fui(fa1.z)), "r"(fui(fa1.w)),
                      "r"(b0a[j]), "r"(b1a[j]));
            }
        }

        if (hasNext) commit(cur ^ 1);
        __syncthreads();
    }

    // ---- epilogue: bias add, store raw, fused BN stats ----
#pragma unroll
    for (int j = 0; j < 4; j++) {
        int c = col0 + wn + 8 * j + 2 * qc;
        float bx = bias[c], by = bias[c + 1];
#pragma unroll
        for (int i = 0; i < 2; i++) {
            acc[i][j][0] += bx; acc[i][j][1] += by;
            acc[i][j][2] += bx; acc[i][j][3] += by;
        }
    }
#pragma unroll
    for (int i = 0; i < 2; i++) {
        int r = row0 + wm + 16 * i + qr;
#pragma unroll
        for (int j = 0; j < 4; j++) {
            int c = col0 + wn + 8 * j + 2 * qc;
            if (r < M)
                *(float2*)(C + (size_t)r * N + c) = make_float2(acc[i][j][0], acc[i][j][1]);
            if (r + 8 < M)
                *(float2*)(C + (size_t)(r + 8) * N + c) = make_float2(acc[i][j][2], acc[i][j][3]);
        }
    }
#pragma unroll
    for (int j = 0; j < 4; j++) {
        float s0 = 0.f, q0 = 0.f, s1 = 0.f, q1 = 0.f;
#pragma unroll
        for (int i = 0; i < 2; i++) {
            int r = row0 + wm + 16 * i + qr;
            if (r < M) {
                s0 += acc[i][j][0]; q0 += acc[i][j][0] * acc[i][j][0];
                s1 += acc[i][j][1]; q1 += acc[i][j][1] * acc[i][j][1];
            }
            if (r + 8 < M) {
                s0 += acc[i][j][2]; q0 += acc[i][j][2] * acc[i][j][2];
                s1 += acc[i][j][3]; q1 += acc[i][j][3] * acc[i][j][3];
            }
        }
#pragma unroll
        for (int off = 4; off < 32; off <<= 1) {
            s0 += __shfl_xor_sync(0xffffffff, s0, off);
            q0 += __shfl_xor_sync(0xffffffff, q0, off);
            s1 += __shfl_xor_sync(0xffffffff, s1, off);
            q1 += __shfl_xor_sync(0xffffffff, q1, off);
        }
        if (qr == 0) {
            int c = col0 + wn + 8 * j + 2 * qc;
            atomicAdd(&g_sums[soff + c], s0);
            atomicAdd(&g_ssqs[soff + c], q0);
            atomicAdd(&g_sums[soff + c + 1], s1);
            atomicAdd(&g_ssqs[soff + c + 1], q1);
        }
    }
}

// ---------------- propagation (ELL by dst; BN+ReLU applied to gathered h) — R8 form ----------------
__global__ void k_prop(int hid, int outid, int F, int coff) {
    const float* h = buf(hid);
    float* out = buf(outid);
    int node = blockIdx.x;
    int t = threadIdx.x;
    int cnt = g_cnt[node];
    int base = node * ELLW;
    float4 sc = make_float4(1.f, 1.f, 1.f, 1.f), sh = make_float4(0.f, 0.f, 0.f, 0.f);
    bool useC = coff >= 0;
    if (useC) {
        sc = *(const float4*)(g_bnsc + coff + t * 4);
        sh = *(const float4*)(g_bnsh + coff + t * 4);
    }
    float4 acc = make_float4(0.f, 0.f, 0.f, 0.f);
    for (int e = 0; e < cnt; e++) {
        int s = g_ell_src[base + e];
        float w = g_ell_w[base + e];
        float4 v = *(const float4*)(h + (size_t)s * F + t * 4);
        if (useC) {
            v.x = fmaxf(fmaf(v.x, sc.x, sh.x), 0.f);
            v.y = fmaxf(fmaf(v.y, sc.y, sh.y), 0.f);
            v.z = fmaxf(fmaf(v.z, sc.z, sh.z), 0.f);
            v.w = fmaxf(fmaf(v.w, sc.w, sh.w), 0.f);
        }
        acc.x += w * v.x; acc.y += w * v.y; acc.z += w * v.z; acc.w += w * v.w;
    }
    *(float4*)(out + (size_t)node * F + t * 4) = acc;
}

__global__ void k_prop_cheb(int hid, int subid, int outid, int F, int subcoff) {
    const float* h = buf(hid);
    const float* sub = buf(subid);
    float* out = buf(outid);
    int node = blockIdx.x;
    int t = threadIdx.x;
    int cnt = g_cnt[node];
    int base = node * ELLW;
    float4 acc = make_float4(0.f, 0.f, 0.f, 0.f);
    for (int e = 0; e < cnt; e++) {
        int s = g_ell_src[base + e];
        float w = g_ell_w[base + e];
        float4 v = *(const float4*)(h + (size_t)s * F + t * 4);
        acc.x += w * v.x; acc.y += w * v.y; acc.z += w * v.z; acc.w += w * v.w;
    }
    float4 sc = *(const float4*)(g_bnsc + subcoff + t * 4);
    float4 sh = *(const float4*)(g_bnsh + subcoff + t * 4);
    float4 sv = *(const float4*)(sub + (size_t)node * F + t * 4);
    sv.x = fmaxf(fmaf(sv.x, sc.x, sh.x), 0.f);
    sv.y = fmaxf(fmaf(sv.y, sc.y, sh.y), 0.f);
    sv.z = fmaxf(fmaf(sv.z, sc.z, sh.z), 0.f);
    sv.w = fmaxf(fmaf(sv.w, sc.w, sh.w), 0.f);
    float4 r;
    r.x = 2.0f * acc.x - sv.x;
    r.y = 2.0f * acc.y - sv.y;
    r.z = 2.0f * acc.z - sv.z;
    r.w = 2.0f * acc.w - sv.w;
    *(float4*)(out + (size_t)node * F + t * 4) = r;
}

// ---------------- fc (bn3 on load; 128 -> 6) + log_softmax ----------------
__global__ void k_fc(const float* __restrict__ W,
                     const float* __restrict__ bias, float* __restrict__ out, int n) {
    const float* h = g_y3;
    int gtid = blockIdx.x * blockDim.x + threadIdx.x;
    int node = gtid >> 5;
    int lane = gtid & 31;
    if (node >= n) return;
    float hv[4];
#pragma unroll
    for (int k = 0; k < 4; k++) {
        int col = lane + 32 * k;
        float raw = h[(size_t)node * 128 + col];
        hv[k] = fmaf(raw, g_bnsc[768 + col], g_bnsh[768 + col]);
    }
    float logit[6];
#pragma unroll
    for (int j = 0; j < 6; j++) {
        float s = 0.0f;
#pragma unroll
        for (int k = 0; k < 4; k++) s += hv[k] * W[(lane + 32 * k) * 6 + j];
#pragma unroll
        for (int o = 16; o > 0; o >>= 1) s += __shfl_xor_sync(0xffffffff, s, o);
        logit[j] = s + bias[j];
    }
    if (lane == 0) {
        float mx = logit[0];
#pragma unroll
        for (int j = 1; j < 6; j++) mx = fmaxf(mx, logit[j]);
        float se = 0.0f;
#pragma unroll
        for (int j = 0; j < 6; j++) se += expf(logit[j] - mx);
        float lse = mx + logf(se);
#pragma unroll
        for (int j = 0; j < 6; j++) out[(size_t)node * 6 + j] = logit[j] - lse;
    }
}

// ---------------- launch ----------------
extern "C" void kernel_launch(void* const* d_in, const int* in_sizes, int n_in,
                              void* d_out, int out_size) {
    const float* x    = (const float*)d_in[0];
    const int*   ei   = (const int*)d_in[1];
    const float* ea   = (const float*)d_in[2];
    const float* W1_0 = (const float*)d_in[3];
    const float* b1   = (const float*)d_in[4];
    const float* g1   = (const float*)d_in[5];
    const float* be1  = (const float*)d_in[6];
    const float* W2_0 = (const float*)d_in[7];
    const float* W2_1 = (const float*)d_in[8];
    const float* b2   = (const float*)d_in[9];
    const float* g2   = (const float*)d_in[10];
    const float* be2  = (const float*)d_in[11];
    const float* W3_0 = (const float*)d_in[12];
    const float* W3_1 = (const float*)d_in[13];
    const float* W3_2 = (const float*)d_in[14];
    const float* b3   = (const float*)d_in[15];
    const float* g3   = (const float*)d_in[16];
    const float* be3  = (const float*)d_in[17];
    const float* fcW  = (const float*)d_in[18];
    const float* fcb  = (const float*)d_in[19];
    float* out = (float*)d_out;

    // ---- one-time B tf32 pre-convert ----
    k_cvtB<<<CEILDIV(768 * 512, 256), 256>>>(W1_0, nullptr, nullptr, 768, 512, 768, 7);
    k_cvtB<<<CEILDIV(1024 * 256, 256), 256>>>(W2_0, W2_1, nullptr, 512, 256, 1024, 8);
    k_cvtB<<<CEILDIV(768 * 128, 256), 256>>>(W3_0, W3_1, W3_2, 256, 128, 768, 9);

    // ---- graph normalization + ELL build ----
    k_init_graph<<<CEILDIV(NN, 256), 256>>>();
    k_deg<<<CEILDIV(EE, 256), 256>>>(ei, ea);
    k_norm_push<<<CEILDIV(EE, 256), 256>>>(ei, ea);

    const int GY = CEILDIV(NN, BMT);   // 157

    // ---- layer 1 ----
    gemm_tf32<<<dim3(512 / BNT, GY), 256>>>(
        x, 0, 0, 0, 7, b1, 1, NN, 512, 768, 1, 0, -1);
    k_bn_coef<<<1, 512>>>(g1, be1, NN, 512, 0);

    // ---- layer 2 ----
    k_prop<<<NN, 128>>>(1, 2, 512, 0);
    gemm_tf32<<<dim3(256 / BNT, GY), 256>>>(
        nullptr, 1, 2, 0, 8, b2, 3, NN, 256, 512, 2, 512, 0);
    k_bn_coef<<<1, 256>>>(g2, be2, NN, 256, 512);

    // ---- layer 3 ----
    k_prop<<<NN, 64>>>(3, 4, 256, 512);
    k_prop_cheb<<<NN, 64>>>(4, 3, 5, 256, 512);
    gemm_tf32<<<dim3(128 / BNT, GY), 256>>>(
        nullptr, 3, 4, 5, 9, b3, 6, NN, 128, 256, 3, 768, 512);
    k_bn_coef<<<1, 128>>>(g3, be3, NN, 128, 768);

    // ---- fc (bn3 fused) + log_softmax ----
    k_fc<<<CEILDIV(NN * 32, 256), 256>>>(fcW, fcb, out, NN);
}

// round 15
// speedup vs baseline: 1.1019x; 1.1019x over previous
#include <cuda_runtime.h>

#define NN 10000
#define EE 160000
#define EPS 1e-5f
#define ELLW 64
#define CEILDIV(a,b) (((a)+(b)-1)/(b))

// ---------------- scratch (static device globals; no allocation) ----------------
__device__ __align__(16) float g_deg[NN];
__device__ __align__(16) int   g_cnt[NN];
__device__ __align__(16) int   g_ell_src[NN * ELLW];
__device__ __align__(16) float g_ell_w[NN * ELLW];
__device__ __align__(16) float g_y1[NN * 512];
__device__ __align__(16) float g_t1[NN * 512];
__device__ __align__(16) float g_y2[NN * 256];
__device__ __align__(16) float g_p2[NN * 256];
__device__ __align__(16) float g_tx2[NN * 256];
__device__ __align__(16) float g_y3[NN * 128];
__device__ __align__(16) float g_tB1[768 * 512];    // tf32-preconverted weights (K-concat)
__device__ __align__(16) float g_tB2[1024 * 256];
__device__ __align__(16) float g_tB3[768 * 128];
__device__ __align__(16) float g_sums[896];
__device__ __align__(16) float g_ssqs[896];
__device__ __align__(16) float g_bnsc[896];
__device__ __align__(16) float g_bnsh[896];

__device__ __forceinline__ float* buf(int id) {
    switch (id) {
        case 1: return g_y1;
        case 2: return g_t1;
        case 3: return g_y2;
        case 4: return g_p2;
        case 5: return g_tx2;
        case 6: return g_y3;
        case 7: return g_tB1;
        case 8: return g_tB2;
        case 9: return g_tB3;
    }
    return nullptr;
}

__device__ __forceinline__ unsigned f2tf(float x) {
    unsigned u;
    asm("cvt.rna.tf32.f32 %0, %1;" : "=r"(u) : "f"(x));
    return u;
}
__device__ __forceinline__ unsigned fui(float x) { return __float_as_uint(x); }

// ---------------- graph build (ELL by dst) ----------------
__global__ void k_init_graph() {
    int i = blockIdx.x * blockDim.x + threadIdx.x;
    if (i < NN) { g_deg[i] = 0.0f; g_cnt[i] = 0; }
    if (i < 896) { g_sums[i] = 0.0f; g_ssqs[i] = 0.0f; }
}
__global__ void k_deg(const int* __restrict__ ei, const float* __restrict__ ea) {
    int e = blockIdx.x * blockDim.x + threadIdx.x;
    if (e >= EE) return;
    atomicAdd(&g_deg[ei[e]], ea[e]);
}
__global__ void k_norm_push(const int* __restrict__ ei, const float* __restrict__ ea) {
    int e = blockIdx.x * blockDim.x + threadIdx.x;
    if (e >= EE) return;
    int s = ei[e];
    int d = ei[EE + e];
    float ds = g_deg[s], dd = g_deg[d];
    float is = (ds > 0.0f) ? rsqrtf(ds) : 0.0f;
    float id = (dd > 0.0f) ? rsqrtf(dd) : 0.0f;
    float w = -is * ea[e] * id;
    int pos = atomicAdd(&g_cnt[d], 1);
    g_ell_src[d * ELLW + pos] = s;
    g_ell_w[d * ELLW + pos] = w;
}

// ---------------- BN coefficients ----------------
__global__ void k_bn_coef(const float* __restrict__ gamma, const float* __restrict__ beta,
                          int n, int F, int soff) {
    int f = threadIdx.x;
    if (f >= F) return;
    float inv_n = 1.0f / (float)n;
    float mu = g_sums[soff + f] * inv_n;
    float var = g_ssqs[soff + f] * inv_n - mu * mu;
    float sc = gamma[f] * rsqrtf(var + EPS);
    g_bnsc[soff + f] = sc;
    g_bnsh[soff + f] = beta[f] - mu * sc;
}

// ---------------- one-time B tf32 pre-convert (+K-concat) ----------------
__global__ void k_cvtB(const float* __restrict__ B0, const float* __restrict__ B1,
                       const float* __restrict__ B2, int Kseg, int N, int K, int dstid) {
    int idx = blockIdx.x * blockDim.x + threadIdx.x;
    if (idx >= K * N) return;
    int row = idx / N;
    int col = idx - row * N;
    int seg = row / Kseg;
    int rloc = row - seg * Kseg;
    const float* B = (seg == 0) ? B0 : (seg == 1) ? B1 : B2;
    buf(dstid)[idx] = __uint_as_float(f2tf(B[rloc * N + col]));
}

// ---------------- tf32 GEMM (R13 inner loop): fragment-major A smem, padded scalar-B smem,
// preconverted B, pointer-walk loop. Template BM: 128 (GEMM1) / 64 (GEMM2,3). ----------------
#define BNT 128
#define BKT 16
#define BPAD 136

template<int BM>
__global__ __launch_bounds__(256, (BM == 64) ? 3 : 2) void gemm_tf32(
    const float* __restrict__ Aext, int aid0, int aid1, int aid2, int tBid,
    const float* __restrict__ bias, int Cid,
    int M, int N, int Kseg, int segs, int soff, int coff0)
{
    constexpr int MI = BM / 32;      // m-subtiles per warp
    constexpr int NF = BM / 16;      // A fragment pages per k-half
    constexpr int AV = BM / 64;      // float4 A-loads per thread
    __shared__ __align__(16) float As[2][2 * NF * 128];
    __shared__ __align__(16) float Bs[2][BKT][BPAD];

    const float* Ap[3];
    Ap[0] = Aext ? Aext : buf(aid0);
    Ap[1] = buf(aid1);
    Ap[2] = buf(aid2);
    float* C = buf(Cid);

    const int tid = threadIdx.x;
    const int lane = tid & 31;
    const int warp = tid >> 5;
    const int qr = lane >> 2;
    const int qc = lane & 3;
    const int wm = (warp & 1) * (BM / 2);
    const int ms0 = (warp & 1) * MI;
    const int wn = (warp >> 1) * 32;

    const int row0 = blockIdx.y * BM;
    const int col0 = blockIdx.x * BNT;

    // A loader: BM=64 -> row=tid/4, akb=(tid&3)*4, 1 float4
    //           BM=128 -> row=tid/2, akb=(tid&1)*8, 2 float4 (k = akb, akb+4)
    const int arow = (BM == 64) ? (tid >> 2) : (tid >> 1);
    const int akb = (BM == 64) ? ((tid & 3) << 2) : ((tid & 1) << 3);
    const bool avalid = (row0 + arow) < M;
    const int wr = arow & 15;
    const int wms = arow >> 4;
    const int xsw = ((wr >> 1) & 3) << 2;
    int awbase[AV];
#pragma unroll
    for (int it = 0; it < AV; it++) {
        int kq = akb + it * 4;
        int wkh = kq >> 3;
        int wkb = (kq >> 2) & 1;
        awbase[it] = (wkh * NF + wms) * 128 + ((wr & 7) << 4) + (wr >> 3) + (wkb << 1);
    }

    // A fragment read base
    const int rpos = (qr << 2) + (qc ^ ((qr >> 1) & 3));
    const int ardbase = ms0 * 128 + (rpos << 2);

    // B loader
    const int brow = tid >> 5;
    const int bcol = (tid & 31) << 2;

    float acc[MI][4][4];
#pragma unroll
    for (int i = 0; i < MI; i++)
#pragma unroll
        for (int j = 0; j < 4; j++)
#pragma unroll
            for (int e = 0; e < 4; e++) acc[i][j][e] = 0.0f;

    // pointer-walk state (no division in main loop)
    const size_t aoff = (size_t)(row0 + arow) * Kseg + akb;
    const float* pA = Ap[0] + aoff;
    const float* psc = g_bnsc + (coff0 >= 0 ? coff0 : 0) + akb;
    const float* psh = g_bnsh + (coff0 >= 0 ? coff0 : 0) + akb;
    const float* pB = buf(tBid) + (size_t)brow * N + col0 + bcol;
    const int bstep = BKT * N;
    int segi = 0, kcnt = 0;
    const int kperseg = Kseg / BKT;
    const int niter = kperseg * segs;

    float4 rA[AV], rB[2];
    auto fetch = [&]() {
#pragma unroll
        for (int it = 0; it < AV; it++) {
            rA[it] = make_float4(0.f, 0.f, 0.f, 0.f);
            if (avalid) rA[it] = *(const float4*)(pA + it * 4);
        }
        if (coff0 >= 0 && segi == 0) {
#pragma unroll
            for (int it = 0; it < AV; it++) {
                float4 sc = *(const float4*)(psc + it * 4);
                float4 sh = *(const float4*)(psh + it * 4);
                rA[it].x = fmaxf(fmaf(rA[it].x, sc.x, sh.x), 0.f);
                rA[it].y = fmaxf(fmaf(rA[it].y, sc.y, sh.y), 0.f);
                rA[it].z = fmaxf(fmaf(rA[it].z, sc.z, sh.z), 0.f);
                rA[it].w = fmaxf(fmaf(rA[it].w, sc.w, sh.w), 0.f);
            }
        }
        rB[0] = *(const float4*)pB;
        rB[1] = *(const float4*)(pB + (size_t)8 * N);
    };
    auto advance = [&]() {
        kcnt++;
        if (kcnt == kperseg) {
            kcnt = 0; segi++;
            if (segi < segs) pA = Ap[segi] + aoff;
        } else {
            pA += BKT;
        }
        psc += BKT; psh += BKT;
        pB += bstep;
    };
    auto commit = [&](int s) {
        float* Aw = As[s];
#pragma unroll
        for (int it = 0; it < AV; it++) {
            Aw[awbase[it] + ((0 << 2) ^ xsw)] = __uint_as_float(f2tf(rA[it].x));
            Aw[awbase[it] + ((1 << 2) ^ xsw)] = __uint_as_float(f2tf(rA[it].y));
            Aw[awbase[it] + ((2 << 2) ^ xsw)] = __uint_as_float(f2tf(rA[it].z));
            Aw[awbase[it] + ((3 << 2) ^ xsw)] = __uint_as_float(f2tf(rA[it].w));
        }
        *(float4*)&Bs[s][brow][bcol] = rB[0];       // already tf32 bits
        *(float4*)&Bs[s][brow + 8][bcol] = rB[1];
    };

    fetch();
    advance();
    commit(0);
    __syncthreads();

    int cur = 0;
    for (int it = 0; it < niter; it++, cur ^= 1) {
        const bool hasNext = (it + 1) < niter;
        if (hasNext) { fetch(); advance(); }

        const float* Ac = As[cur];
        const float* Bc = &Bs[cur][0][0];
#pragma unroll
        for (int kh = 0; kh < 2; kh++) {
            const float* Af = Ac + kh * (NF * 128) + ardbase;
            float4 fa[MI];
#pragma unroll
            for (int i = 0; i < MI; i++) fa[i] = *(const float4*)(Af + i * 128);
            const float* Bk0 = Bc + (kh * 8 + qc) * BPAD + wn + qr;
            const float* Bk1 = Bk0 + 4 * BPAD;
#pragma unroll
            for (int j = 0; j < 4; j++) {
                unsigned b0 = fui(Bk0[8 * j]);
                unsigned b1 = fui(Bk1[8 * j]);
#pragma unroll
                for (int i = 0; i < MI; i++) {
                    asm volatile(
                        "mma.sync.aligned.m16n8k8.row.col.f32.tf32.tf32.f32 "
                        "{%0,%1,%2,%3}, {%4,%5,%6,%7}, {%8,%9}, {%0,%1,%2,%3};"
                        : "+f"(acc[i][j][0]), "+f"(acc[i][j][1]),
                          "+f"(acc[i][j][2]), "+f"(acc[i][j][3])
                        : "r"(fui(fa[i].x)), "r"(fui(fa[i].y)), "r"(fui(fa[i].z)), "r"(fui(fa[i].w)),
                          "r"(b0), "r"(b1));
                }
            }
        }

        if (hasNext) commit(cur ^ 1);
        __syncthreads();
    }

    // ---- epilogue: bias add, store raw, fused BN stats ----
#pragma unroll
    for (int j = 0; j < 4; j++) {
        int c = col0 + wn + 8 * j + 2 * qc;
        float bx = bias[c], by = bias[c + 1];
#pragma unroll
        for (int i = 0; i < MI; i++) {
            acc[i][j][0] += bx; acc[i][j][1] += by;
            acc[i][j][2] += bx; acc[i][j][3] += by;
        }
    }
#pragma unroll
    for (int i = 0; i < MI; i++) {
        int r = row0 + wm + 16 * i + qr;
#pragma unroll
        for (int j = 0; j < 4; j++) {
            int c = col0 + wn + 8 * j + 2 * qc;
            if (r < M)
                *(float2*)(C + (size_t)r * N + c) = make_float2(acc[i][j][0], acc[i][j][1]);
            if (r + 8 < M)
                *(float2*)(C + (size_t)(r + 8) * N + c) = make_float2(acc[i][j][2], acc[i][j][3]);
        }
    }
#pragma unroll
    for (int j = 0; j < 4; j++) {
        float s0 = 0.f, q0 = 0.f, s1 = 0.f, q1 = 0.f;
#pragma unroll
        for (int i = 0; i < MI; i++) {
            int r = row0 + wm + 16 * i + qr;
            if (r < M) {
                s0 += acc[i][j][0]; q0 += acc[i][j][0] * acc[i][j][0];
                s1 += acc[i][j][1]; q1 += acc[i][j][1] * acc[i][j][1];
            }
            if (r + 8 < M) {
                s0 += acc[i][j][2]; q0 += acc[i][j][2] * acc[i][j][2];
                s1 += acc[i][j][3]; q1 += acc[i][j][3] * acc[i][j][3];
            }
        }
#pragma unroll
        for (int off = 4; off < 32; off <<= 1) {
            s0 += __shfl_xor_sync(0xffffffff, s0, off);
            q0 += __shfl_xor_sync(0xffffffff, q0, off);
            s1 += __shfl_xor_sync(0xffffffff, s1, off);
            q1 += __shfl_xor_sync(0xffffffff, q1, off);
        }
        if (qr == 0) {
            int c = col0 + wn + 8 * j + 2 * qc;
            atomicAdd(&g_sums[soff + c], s0);
            atomicAdd(&g_ssqs[soff + c], q0);
            atomicAdd(&g_sums[soff + c + 1], s1);
            atomicAdd(&g_ssqs[soff + c + 1], q1);
        }
    }
}

// ---------------- propagation (ELL by dst; BN+ReLU applied to gathered h) — R8 form ----------------
__global__ void k_prop(int hid, int outid, int F, int coff) {
    const float* h = buf(hid);
    float* out = buf(outid);
    int node = blockIdx.x;
    int t = threadIdx.x;
    int cnt = g_cnt[node];
    int base = node * ELLW;
    float4 sc = make_float4(1.f, 1.f, 1.f, 1.f), sh = make_float4(0.f, 0.f, 0.f, 0.f);
    bool useC = coff >= 0;
    if (useC) {
        sc = *(const float4*)(g_bnsc + coff + t * 4);
        sh = *(const float4*)(g_bnsh + coff + t * 4);
    }
    float4 acc = make_float4(0.f, 0.f, 0.f, 0.f);
    for (int e = 0; e < cnt; e++) {
        int s = g_ell_src[base + e];
        float w = g_ell_w[base + e];
        float4 v = *(const float4*)(h + (size_t)s * F + t * 4);
        if (useC) {
            v.x = fmaxf(fmaf(v.x, sc.x, sh.x), 0.f);
            v.y = fmaxf(fmaf(v.y, sc.y, sh.y), 0.f);
            v.z = fmaxf(fmaf(v.z, sc.z, sh.z), 0.f);
            v.w = fmaxf(fmaf(v.w, sc.w, sh.w), 0.f);
        }
        acc.x += w * v.x; acc.y += w * v.y; acc.z += w * v.z; acc.w += w * v.w;
    }
    *(float4*)(out + (size_t)node * F + t * 4) = acc;
}

__global__ void k_prop_cheb(int hid, int subid, int outid, int F, int subcoff) {
    const float* h = buf(hid);
    const float* sub = buf(subid);
    float* out = buf(outid);
    int node = blockIdx.x;
    int t = threadIdx.x;
    int cnt = g_cnt[node];
    int base = node * ELLW;
    float4 acc = make_float4(0.f, 0.f, 0.f, 0.f);
    for (int e = 0; e < cnt; e++) {
        int s = g_ell_src[base + e];
        float w = g_ell_w[base + e];
        float4 v = *(const float4*)(h + (size_t)s * F + t * 4);
        acc.x += w * v.x; acc.y += w * v.y; acc.z += w * v.z; acc.w += w * v.w;
    }
    float4 sc = *(const float4*)(g_bnsc + subcoff + t * 4);
    float4 sh = *(const float4*)(g_bnsh + subcoff + t * 4);
    float4 sv = *(const float4*)(sub + (size_t)node * F + t * 4);
    sv.x = fmaxf(fmaf(sv.x, sc.x, sh.x), 0.f);
    sv.y = fmaxf(fmaf(sv.y, sc.y, sh.y), 0.f);
    sv.z = fmaxf(fmaf(sv.z, sc.z, sh.z), 0.f);
    sv.w = fmaxf(fmaf(sv.w, sc.w, sh.w), 0.f);
    float4 r;
    r.x = 2.0f * acc.x - sv.x;
    r.y = 2.0f * acc.y - sv.y;
    r.z = 2.0f * acc.z - sv.z;
    r.w = 2.0f * acc.w - sv.w;
    *(float4*)(out + (size_t)node * F + t * 4) = r;
}

// ---------------- fc (bn3 on load; 128 -> 6) + log_softmax ----------------
__global__ void k_fc(const float* __restrict__ W,
                     const float* __restrict__ bias, float* __restrict__ out, int n) {
    const float* h = g_y3;
    int gtid = blockIdx.x * blockDim.x + threadIdx.x;
    int node = gtid >> 5;
    int lane = gtid & 31;
    if (node >= n) return;
    float hv[4];
#pragma unroll
    for (int k = 0; k < 4; k++) {
        int col = lane + 32 * k;
        float raw = h[(size_t)node * 128 + col];
        hv[k] = fmaf(raw, g_bnsc[768 + col], g_bnsh[768 + col]);
    }
    float logit[6];
#pragma unroll
    for (int j = 0; j < 6; j++) {
        float s = 0.0f;
#pragma unroll
        for (int k = 0; k < 4; k++) s += hv[k] * W[(lane + 32 * k) * 6 + j];
#pragma unroll
        for (int o = 16; o > 0; o >>= 1) s += __shfl_xor_sync(0xffffffff, s, o);
        logit[j] = s + bias[j];
    }
    if (lane == 0) {
        float mx = logit[0];
#pragma unroll
        for (int j = 1; j < 6; j++) mx = fmaxf(mx, logit[j]);
        float se = 0.0f;
#pragma unroll
        for (int j = 0; j < 6; j++) se += expf(logit[j] - mx);
        float lse = mx + logf(se);
#pragma unroll
        for (int j = 0; j < 6; j++) out[(size_t)node * 6 + j] = logit[j] - lse;
    }
}

// ---------------- launch ----------------
extern "C" void kernel_launch(void* const* d_in, const int* in_sizes, int n_in,
                              void* d_out, int out_size) {
    const float* x    = (const float*)d_in[0];
    const int*   ei   = (const int*)d_in[1];
    const float* ea   = (const float*)d_in[2];
    const float* W1_0 = (const float*)d_in[3];
    const float* b1   = (const float*)d_in[4];
    const float* g1   = (const float*)d_in[5];
    const float* be1  = (const float*)d_in[6];
    const float* W2_0 = (const float*)d_in[7];
    const float* W2_1 = (const float*)d_in[8];
    const float* b2   = (const float*)d_in[9];
    const float* g2   = (const float*)d_in[10];
    const float* be2  = (const float*)d_in[11];
    const float* W3_0 = (const float*)d_in[12];
    const float* W3_1 = (const float*)d_in[13];
    const float* W3_2 = (const float*)d_in[14];
    const float* b3   = (const float*)d_in[15];
    const float* g3   = (const float*)d_in[16];
    const float* be3  = (const float*)d_in[17];
    const float* fcW  = (const float*)d_in[18];
    const float* fcb  = (const float*)d_in[19];
    float* out = (float*)d_out;

    // ---- one-time B tf32 pre-convert ----
    k_cvtB<<<CEILDIV(768 * 512, 256), 256>>>(W1_0, nullptr, nullptr, 768, 512, 768, 7);
    k_cvtB<<<CEILDIV(1024 * 256, 256), 256>>>(W2_0, W2_1, nullptr, 512, 256, 1024, 8);
    k_cvtB<<<CEILDIV(768 * 128, 256), 256>>>(W3_0, W3_1, W3_2, 256, 128, 768, 9);

    // ---- graph normalization + ELL build ----
    k_init_graph<<<CEILDIV(NN, 256), 256>>>();
    k_deg<<<CEILDIV(EE, 256), 256>>>(ei, ea);
    k_norm_push<<<CEILDIV(EE, 256), 256>>>(ei, ea);

    // ---- layer 1: BM=128 (better LDS/MMA ratio; 316 CTAs @2/SM = 1.07 waves) ----
    gemm_tf32<128><<<dim3(512 / BNT, CEILDIV(NN, 128)), 256>>>(
        x, 0, 0, 0, 7, b1, 1, NN, 512, 768, 1, 0, -1);
    k_bn_coef<<<1, 512>>>(g1, be1, NN, 512, 0);

    // ---- layer 2: BM=64 ----
    k_prop<<<NN, 128>>>(1, 2, 512, 0);
    gemm_tf32<64><<<dim3(256 / BNT, CEILDIV(NN, 64)), 256>>>(
        nullptr, 1, 2, 0, 8, b2, 3, NN, 256, 512, 2, 512, 0);
    k_bn_coef<<<1, 256>>>(g2, be2, NN, 256, 512);

    // ---- layer 3: BM=64 ----
    k_prop<<<NN, 64>>>(3, 4, 256, 512);
    k_prop_cheb<<<NN, 64>>>(4, 3, 5, 256, 512);
    gemm_tf32<64><<<dim3(128 / BNT, CEILDIV(NN, 64)), 256>>>(
        nullptr, 3, 4, 5, 9, b3, 6, NN, 128, 256, 3, 768, 512);
    k_bn_coef<<<1, 128>>>(g3, be3, NN, 128, 768);

    // ---- fc (bn3 fused) + log_softmax ----
    k_fc<<<CEILDIV(NN * 32, 256), 256>>>(fcW, fcb, out, NN);
}

// round 16
// speedup vs baseline: 1.1419x; 1.0363x over previous
#include <cuda_runtime.h>

#define NN 10000
#define EE 160000
#define EPS 1e-5f
#define ELLW 64
#define CEILDIV(a,b) (((a)+(b)-1)/(b))

// ---------------- scratch (static device globals; no allocation) ----------------
__device__ __align__(16) float g_deg[NN];
__device__ __align__(16) int   g_cnt[NN];
__device__ __align__(16) int   g_ell_src[NN * ELLW];
__device__ __align__(16) float g_ell_w[NN * ELLW];
__device__ __align__(16) float g_y1[NN * 512];
__device__ __align__(16) float g_t1[NN * 512];
__device__ __align__(16) float g_y2[NN * 256];
__device__ __align__(16) float g_p2[NN * 256];
__device__ __align__(16) float g_tx2[NN * 256];
__device__ __align__(16) float g_y3[NN * 128];
__device__ __align__(16) float g_tB1[768 * 512];    // tf32-preconverted weights (K-concat)
__device__ __align__(16) float g_tB2[1024 * 256];
__device__ __align__(16) float g_tB3[768 * 128];
__device__ __align__(16) float g_sums[896];
__device__ __align__(16) float g_ssqs[896];
__device__ __align__(16) float g_bnsc[896];
__device__ __align__(16) float g_bnsh[896];

__device__ __forceinline__ float* buf(int id) {
    switch (id) {
        case 1: return g_y1;
        case 2: return g_t1;
        case 3: return g_y2;
        case 4: return g_p2;
        case 5: return g_tx2;
        case 6: return g_y3;
        case 7: return g_tB1;
        case 8: return g_tB2;
        case 9: return g_tB3;
    }
    return nullptr;
}

__device__ __forceinline__ unsigned f2tf(float x) {
    unsigned u;
    asm("cvt.rna.tf32.f32 %0, %1;" : "=r"(u) : "f"(x));
    return u;
}
__device__ __forceinline__ unsigned fui(float x) { return __float_as_uint(x); }

// ---------------- fused prep: init graph/sums + tf32 pre-convert all weights ----------------
#define B1E (768 * 512)          // 393216
#define B2E (1024 * 256)         // 262144
#define B3E (768 * 128)          // 98304
#define PREPE (B1E + B2E + B3E)  // 753664
__global__ void k_prep(const float* __restrict__ W1_0,
                       const float* __restrict__ W2_0, const float* __restrict__ W2_1,
                       const float* __restrict__ W3_0, const float* __restrict__ W3_1,
                       const float* __restrict__ W3_2) {
    int idx = blockIdx.x * blockDim.x + threadIdx.x;
    if (idx < NN) { g_deg[idx] = 0.0f; g_cnt[idx] = 0; }
    if (idx < 896) { g_sums[idx] = 0.0f; g_ssqs[idx] = 0.0f; }
    if (idx < B1E) {
        g_tB1[idx] = __uint_as_float(f2tf(W1_0[idx]));           // K=768, N=512, 1 seg
    } else if (idx < B1E + B2E) {
        int i2 = idx - B1E;                                       // K=1024, N=256, Kseg=512
        int row = i2 >> 8;
        int col = i2 & 255;
        const float* B = (row < 512) ? W2_0 : W2_1;
        g_tB2[i2] = __uint_as_float(f2tf(B[(row & 511) * 256 + col]));
    } else if (idx < PREPE) {
        int i3 = idx - B1E - B2E;                                 // K=768, N=128, Kseg=256
        int row = i3 >> 7;
        int col = i3 & 127;
        int seg = row >> 8;
        const float* B = (seg == 0) ? W3_0 : (seg == 1) ? W3_1 : W3_2;
        g_tB3[i3] = __uint_as_float(f2tf(B[(row & 255) * 128 + col]));
    }
}

// ---------------- graph build (ELL by dst) ----------------
__global__ void k_deg(const int* __restrict__ ei, const float* __restrict__ ea) {
    int e = blockIdx.x * blockDim.x + threadIdx.x;
    if (e >= EE) return;
    atomicAdd(&g_deg[ei[e]], ea[e]);
}
__global__ void k_norm_push(const int* __restrict__ ei, const float* __restrict__ ea) {
    int e = blockIdx.x * blockDim.x + threadIdx.x;
    if (e >= EE) return;
    int s = ei[e];
    int d = ei[EE + e];
    float ds = g_deg[s], dd = g_deg[d];
    float is = (ds > 0.0f) ? rsqrtf(ds) : 0.0f;
    float id = (dd > 0.0f) ? rsqrtf(dd) : 0.0f;
    float w = -is * ea[e] * id;
    int pos = atomicAdd(&g_cnt[d], 1);
    g_ell_src[d * ELLW + pos] = s;
    g_ell_w[d * ELLW + pos] = w;
}

// ---------------- BN coefficients (layers 1,2) ----------------
__global__ void k_bn_coef(const float* __restrict__ gamma, const float* __restrict__ beta,
                          int n, int F, int soff) {
    int f = threadIdx.x;
    if (f >= F) return;
    float inv_n = 1.0f / (float)n;
    float mu = g_sums[soff + f] * inv_n;
    float var = g_ssqs[soff + f] * inv_n - mu * mu;
    float sc = gamma[f] * rsqrtf(var + EPS);
    g_bnsc[soff + f] = sc;
    g_bnsh[soff + f] = beta[f] - mu * sc;
}

// ---------------- tf32 GEMM (R13-exact): BM=64, BN=128, BKT=16; fragment-major A smem,
// padded scalar-B smem, preconverted B, pointer-walk loop ----------------
#define BMT 64
#define BNT 128
#define BKT 16
#define NF 4
#define A_STAGE (2 * NF * 128)   // 1024 floats
#define BPAD 136

__global__ __launch_bounds__(256, 3) void gemm_tf32(
    const float* __restrict__ Aext, int aid0, int aid1, int aid2, int tBid,
    const float* __restrict__ bias, int Cid,
    int M, int N, int Kseg, int segs, int soff, int coff0)
{
    __shared__ __align__(16) float As[2][A_STAGE];
    __shared__ __align__(16) float Bs[2][BKT][BPAD];

    const float* Ap[3];
    Ap[0] = Aext ? Aext : buf(aid0);
    Ap[1] = buf(aid1);
    Ap[2] = buf(aid2);
    float* C = buf(Cid);

    const int tid = threadIdx.x;
    const int lane = tid & 31;
    const int warp = tid >> 5;
    const int qr = lane >> 2;
    const int qc = lane & 3;
    const int wm = (warp & 1) * 32;
    const int ms0 = (warp & 1) * 2;
    const int wn = (warp >> 1) * 32;

    const int row0 = blockIdx.y * BMT;
    const int col0 = blockIdx.x * BNT;

    // A loader: one float4 per thread: row=tid/4, k=(tid&3)*4
    const int arow = tid >> 2;
    const int ak = (tid & 3) << 2;
    const bool avalid = (row0 + arow) < M;
    const int wr = arow & 15;
    const int wms = arow >> 4;
    const int wkh = ak >> 3;
    const int wkb = (ak >> 2) & 1;
    const int xsw = ((wr >> 1) & 3) << 2;
    const int awbase = (wkh * NF + wms) * 128 + ((wr & 7) << 4) + (wr >> 3) + (wkb << 1);

    // A fragment read base
    const int rpos = (qr << 2) + (qc ^ ((qr >> 1) & 3));
    const int ardbase = ms0 * 128 + (rpos << 2);

    // B loader
    const int brow = tid >> 5;
    const int bcol = (tid & 31) << 2;

    float acc[2][4][4];
#pragma unroll
    for (int i = 0; i < 2; i++)
#pragma unroll
        for (int j = 0; j < 4; j++)
#pragma unroll
            for (int e = 0; e < 4; e++) acc[i][j][e] = 0.0f;

    // pointer-walk state (no division in main loop)
    const size_t aoff = (size_t)(row0 + arow) * Kseg + ak;
    const float* pA = Ap[0] + aoff;
    const float* psc = g_bnsc + (coff0 >= 0 ? coff0 : 0) + ak;
    const float* psh = g_bnsh + (coff0 >= 0 ? coff0 : 0) + ak;
    const float* pB = buf(tBid) + (size_t)brow * N + col0 + bcol;
    const int bstep = BKT * N;
    int segi = 0, kcnt = 0;
    const int kperseg = Kseg / BKT;
    const int niter = kperseg * segs;

    float4 rA, rB[2];
    auto fetch = [&]() {
        rA = make_float4(0.f, 0.f, 0.f, 0.f);
        if (avalid) rA = *(const float4*)pA;
        if (coff0 >= 0 && segi == 0) {
            float4 sc = *(const float4*)psc;
            float4 sh = *(const float4*)psh;
            rA.x = fmaxf(fmaf(rA.x, sc.x, sh.x), 0.f);
            rA.y = fmaxf(fmaf(rA.y, sc.y, sh.y), 0.f);
            rA.z = fmaxf(fmaf(rA.z, sc.z, sh.z), 0.f);
            rA.w = fmaxf(fmaf(rA.w, sc.w, sh.w), 0.f);
        }
        rB[0] = *(const float4*)pB;
        rB[1] = *(const float4*)(pB + (size_t)8 * N);
    };
    auto advance = [&]() {
        kcnt++;
        if (kcnt == kperseg) {
            kcnt = 0; segi++;
            if (segi < segs) pA = Ap[segi] + aoff;
        } else {
            pA += BKT;
        }
        psc += BKT; psh += BKT;
        pB += bstep;
    };
    auto commit = [&](int s) {
        float* Aw = As[s];
        Aw[awbase + ((0 << 2) ^ xsw)] = __uint_as_float(f2tf(rA.x));
        Aw[awbase + ((1 << 2) ^ xsw)] = __uint_as_float(f2tf(rA.y));
        Aw[awbase + ((2 << 2) ^ xsw)] = __uint_as_float(f2tf(rA.z));
        Aw[awbase + ((3 << 2) ^ xsw)] = __uint_as_float(f2tf(rA.w));
        *(float4*)&Bs[s][brow][bcol] = rB[0];       // already tf32 bits
        *(float4*)&Bs[s][brow + 8][bcol] = rB[1];
    };

    fetch();
    advance();
    commit(0);
    __syncthreads();

    int cur = 0;
    for (int it = 0; it < niter; it++, cur ^= 1) {
        const bool hasNext = (it + 1) < niter;
        if (hasNext) { fetch(); advance(); }

        const float* Ac = As[cur];
        const float* Bc = &Bs[cur][0][0];
#pragma unroll
        for (int kh = 0; kh < 2; kh++) {
            const float* Af = Ac + kh * (NF * 128) + ardbase;
            float4 fa0 = *(const float4*)(Af);
            float4 fa1 = *(const float4*)(Af + 128);
            const float* Bk0 = Bc + (kh * 8 + qc) * BPAD + wn + qr;
            const float* Bk1 = Bk0 + 4 * BPAD;
#pragma unroll
            for (int j = 0; j < 4; j++) {
                unsigned b0 = fui(Bk0[8 * j]);
                unsigned b1 = fui(Bk1[8 * j]);
                asm volatile(
                    "mma.sync.aligned.m16n8k8.row.col.f32.tf32.tf32.f32 "
                    "{%0,%1,%2,%3}, {%4,%5,%6,%7}, {%8,%9}, {%0,%1,%2,%3};"
                    : "+f"(acc[0][j][0]), "+f"(acc[0][j][1]),
                      "+f"(acc[0][j][2]), "+f"(acc[0][j][3])
                    : "r"(fui(fa0.x)), "r"(fui(fa0.y)), "r"(fui(fa0.z)), "r"(fui(fa0.w)),
                      "r"(b0), "r"(b1));
                asm volatile(
                    "mma.sync.aligned.m16n8k8.row.col.f32.tf32.tf32.f32 "
                    "{%0,%1,%2,%3}, {%4,%5,%6,%7}, {%8,%9}, {%0,%1,%2,%3};"
                    : "+f"(acc[1][j][0]), "+f"(acc[1][j][1]),
                      "+f"(acc[1][j][2]), "+f"(acc[1][j][3])
                    : "r"(fui(fa1.x)), "r"(fui(fa1.y)), "r"(fui(fa1.z)), "r"(fui(fa1.w)),
                      "r"(b0), "r"(b1));
            }
        }

        if (hasNext) commit(cur ^ 1);
        __syncthreads();
    }

    // ---- epilogue: bias add, store raw, fused BN stats ----
#pragma unroll
    for (int j = 0; j < 4; j++) {
        int c = col0 + wn + 8 * j + 2 * qc;
        float bx = bias[c], by = bias[c + 1];
#pragma unroll
        for (int i = 0; i < 2; i++) {
            acc[i][j][0] += bx; acc[i][j][1] += by;
            acc[i][j][2] += bx; acc[i][j][3] += by;
        }
    }
#pragma unroll
    for (int i = 0; i < 2; i++) {
        int r = row0 + wm + 16 * i + qr;
#pragma unroll
        for (int j = 0; j < 4; j++) {
            int c = col0 + wn + 8 * j + 2 * qc;
            if (r < M)
                *(float2*)(C + (size_t)r * N + c) = make_float2(acc[i][j][0], acc[i][j][1]);
            if (r + 8 < M)
                *(float2*)(C + (size_t)(r + 8) * N + c) = make_float2(acc[i][j][2], acc[i][j][3]);
        }
    }
#pragma unroll
    for (int j = 0; j < 4; j++) {
        float s0 = 0.f, q0 = 0.f, s1 = 0.f, q1 = 0.f;
#pragma unroll
        for (int i = 0; i < 2; i++) {
            int r = row0 + wm + 16 * i + qr;
            if (r < M) {
                s0 += acc[i][j][0]; q0 += acc[i][j][0] * acc[i][j][0];
                s1 += acc[i][j][1]; q1 += acc[i][j][1] * acc[i][j][1];
            }
            if (r + 8 < M) {
                s0 += acc[i][j][2]; q0 += acc[i][j][2] * acc[i][j][2];
                s1 += acc[i][j][3]; q1 += acc[i][j][3] * acc[i][j][3];
            }
        }
#pragma unroll
        for (int off = 4; off < 32; off <<= 1) {
            s0 += __shfl_xor_sync(0xffffffff, s0, off);
            q0 += __shfl_xor_sync(0xffffffff, q0, off);
            s1 += __shfl_xor_sync(0xffffffff, s1, off);
            q1 += __shfl_xor_sync(0xffffffff, q1, off);
        }
        if (qr == 0) {
            int c = col0 + wn + 8 * j + 2 * qc;
            atomicAdd(&g_sums[soff + c], s0);
            atomicAdd(&g_ssqs[soff + c], q0);
            atomicAdd(&g_sums[soff + c + 1], s1);
            atomicAdd(&g_ssqs[soff + c + 1], q1);
        }
    }
}

// ---------------- propagation (ELL by dst; BN+ReLU applied to gathered h) — R8 form ----------------
__global__ void k_prop(int hid, int outid, int F, int coff) {
    const float* h = buf(hid);
    float* out = buf(outid);
    int node = blockIdx.x;
    int t = threadIdx.x;
    int cnt = g_cnt[node];
    int base = node * ELLW;
    float4 sc = make_float4(1.f, 1.f, 1.f, 1.f), sh = make_float4(0.f, 0.f, 0.f, 0.f);
    bool useC = coff >= 0;
    if (useC) {
        sc = *(const float4*)(g_bnsc + coff + t * 4);
        sh = *(const float4*)(g_bnsh + coff + t * 4);
    }
    float4 acc = make_float4(0.f, 0.f, 0.f, 0.f);
    for (int e = 0; e < cnt; e++) {
        int s = g_ell_src[base + e];
        float w = g_ell_w[base + e];
        float4 v = *(const float4*)(h + (size_t)s * F + t * 4);
        if (useC) {
            v.x = fmaxf(fmaf(v.x, sc.x, sh.x), 0.f);
            v.y = fmaxf(fmaf(v.y, sc.y, sh.y), 0.f);
            v.z = fmaxf(fmaf(v.z, sc.z, sh.z), 0.f);
            v.w = fmaxf(fmaf(v.w, sc.w, sh.w), 0.f);
        }
        acc.x += w * v.x; acc.y += w * v.y; acc.z += w * v.z; acc.w += w * v.w;
    }
    *(float4*)(out + (size_t)node * F + t * 4) = acc;
}

__global__ void k_prop_cheb(int hid, int subid, int outid, int F, int subcoff) {
    const float* h = buf(hid);
    const float* sub = buf(subid);
    float* out = buf(outid);
    int node = blockIdx.x;
    int t = threadIdx.x;
    int cnt = g_cnt[node];
    int base = node * ELLW;
    float4 acc = make_float4(0.f, 0.f, 0.f, 0.f);
    for (int e = 0; e < cnt; e++) {
        int s = g_ell_src[base + e];
        float w = g_ell_w[base + e];
        float4 v = *(const float4*)(h + (size_t)s * F + t * 4);
        acc.x += w * v.x; acc.y += w * v.y; acc.z += w * v.z; acc.w += w * v.w;
    }
    float4 sc = *(const float4*)(g_bnsc + subcoff + t * 4);
    float4 sh = *(const float4*)(g_bnsh + subcoff + t * 4);
    float4 sv = *(const float4*)(sub + (size_t)node * F + t * 4);
    sv.x = fmaxf(fmaf(sv.x, sc.x, sh.x), 0.f);
    sv.y = fmaxf(fmaf(sv.y, sc.y, sh.y), 0.f);
    sv.z = fmaxf(fmaf(sv.z, sc.z, sh.z), 0.f);
    sv.w = fmaxf(fmaf(sv.w, sc.w, sh.w), 0.f);
    float4 r;
    r.x = 2.0f * acc.x - sv.x;
    r.y = 2.0f * acc.y - sv.y;
    r.z = 2.0f * acc.z - sv.z;
    r.w = 2.0f * acc.w - sv.w;
    *(float4*)(out + (size_t)node * F + t * 4) = r;
}

// ---------------- fc (bn3 coefs computed inline; 128 -> 6) + log_softmax ----------------
__global__ void k_fc(const float* __restrict__ W, const float* __restrict__ bias,
                     const float* __restrict__ gamma3, const float* __restrict__ beta3,
                     float* __restrict__ out, int n) {
    const float* h = g_y3;
    int gtid = blockIdx.x * blockDim.x + threadIdx.x;
    int node = gtid >> 5;
    int lane = gtid & 31;
    if (node >= n) return;
    const float inv_n = 1.0f / (float)n;
    float hv[4];
#pragma unroll
    for (int k = 0; k < 4; k++) {
        int col = lane + 32 * k;
        float mu = g_sums[768 + col] * inv_n;
        float var = g_ssqs[768 + col] * inv_n - mu * mu;
        float sc = gamma3[col] * rsqrtf(var + EPS);
        float shv = beta3[col] - mu * sc;
        float raw = h[(size_t)node * 128 + col];
        hv[k] = fmaf(raw, sc, shv);
    }
    float logit[6];
#pragma unroll
    for (int j = 0; j < 6; j++) {
        float s = 0.0f;
#pragma unroll
        for (int k = 0; k < 4; k++) s += hv[k] * W[(lane + 32 * k) * 6 + j];
#pragma unroll
        for (int o = 16; o > 0; o >>= 1) s += __shfl_xor_sync(0xffffffff, s, o);
        logit[j] = s + bias[j];
    }
    if (lane == 0) {
        float mx = logit[0];
#pragma unroll
        for (int j = 1; j < 6; j++) mx = fmaxf(mx, logit[j]);
        float se = 0.0f;
#pragma unroll
        for (int j = 0; j < 6; j++) se += expf(logit[j] - mx);
        float lse = mx + logf(se);
#pragma unroll
        for (int j = 0; j < 6; j++) out[(size_t)node * 6 + j] = logit[j] - lse;
    }
}

// ---------------- launch ----------------
extern "C" void kernel_launch(void* const* d_in, const int* in_sizes, int n_in,
                              void* d_out, int out_size) {
    const float* x    = (const float*)d_in[0];
    const int*   ei   = (const int*)d_in[1];
    const float* ea   = (const float*)d_in[2];
    const float* W1_0 = (const float*)d_in[3];
    const float* b1   = (const float*)d_in[4];
    const float* g1   = (const float*)d_in[5];
    const float* be1  = (const float*)d_in[6];
    const float* W2_0 = (const float*)d_in[7];
    const float* W2_1 = (const float*)d_in[8];
    const float* b2   = (const float*)d_in[9];
    const float* g2   = (const float*)d_in[10];
    const float* be2  = (const float*)d_in[11];
    const float* W3_0 = (const float*)d_in[12];
    const float* W3_1 = (const float*)d_in[13];
    const float* W3_2 = (const float*)d_in[14];
    const float* b3   = (const float*)d_in[15];
    const float* g3   = (const float*)d_in[16];
    const float* be3  = (const float*)d_in[17];
    const float* fcW  = (const float*)d_in[18];
    const float* fcb  = (const float*)d_in[19];
    float* out = (float*)d_out;

    // ---- fused prep: init + weight tf32 pre-convert (1 launch) ----
    k_prep<<<CEILDIV(PREPE, 256), 256>>>(W1_0, W2_0, W2_1, W3_0, W3_1, W3_2);

    // ---- graph normalization + ELL build ----
    k_deg<<<CEILDIV(EE, 256), 256>>>(ei, ea);
    k_norm_push<<<CEILDIV(EE, 256), 256>>>(ei, ea);

    const int GY = CEILDIV(NN, BMT);   // 157

    // ---- layer 1 ----
    gemm_tf32<<<dim3(512 / BNT, GY), 256>>>(
        x, 0, 0, 0, 7, b1, 1, NN, 512, 768, 1, 0, -1);
    k_bn_coef<<<1, 512>>>(g1, be1, NN, 512, 0);

    // ---- layer 2 ----
    k_prop<<<NN, 128>>>(1, 2, 512, 0);
    gemm_tf32<<<dim3(256 / BNT, GY), 256>>>(
        nullptr, 1, 2, 0, 8, b2, 3, NN, 256, 512, 2, 512, 0);
    k_bn_coef<<<1, 256>>>(g2, be2, NN, 256, 512);

    // ---- layer 3 ----
    k_prop<<<NN, 64>>>(3, 4, 256, 512);
    k_prop_cheb<<<NN, 64>>>(4, 3, 5, 256, 512);
    gemm_tf32<<<dim3(128 / BNT, GY), 256>>>(
        nullptr, 3, 4, 5, 9, b3, 6, NN, 128, 256, 3, 768, 512);

    // ---- fc (bn3 coefs inline) + log_softmax ----
    k_fc<<<CEILDIV(NN * 32, 256), 256>>>(fcW, fcb, g3, be3, out, NN);
}

// round 17
// speedup vs baseline: 1.1736x; 1.0277x over previous
#include <cuda_runtime.h>

#define NN 10000
#define EE 160000
#define EPS 1e-5f
#define ELLW 64
#define CEILDIV(a,b) (((a)+(b)-1)/(b))

// ---------------- scratch (static device globals; no allocation) ----------------
__device__ __align__(16) float g_deg[NN];
__device__ __align__(16) int   g_cnt[NN];
__device__ __align__(16) int   g_ell_src[NN * ELLW];
__device__ __align__(16) float g_ell_w[NN * ELLW];
__device__ __align__(16) float g_y1[NN * 512];
__device__ __align__(16) float g_t1[NN * 512];
__device__ __align__(16) float g_y2[NN * 256];
__device__ __align__(16) float g_p2[NN * 256];
__device__ __align__(16) float g_tx2[NN * 256];
__device__ __align__(16) float g_y3[NN * 128];
__device__ __align__(16) float g_tB1[768 * 512];    // tf32-preconverted weights (K-concat)
__device__ __align__(16) float g_tB2[1024 * 256];
__device__ __align__(16) float g_tB3[768 * 128];
__device__ __align__(16) float g_sums[896];
__device__ __align__(16) float g_ssqs[896];
__device__ __align__(16) float g_bnsc[896];
__device__ __align__(16) float g_bnsh[896];

__device__ __forceinline__ float* buf(int id) {
    switch (id) {
        case 1: return g_y1;
        case 2: return g_t1;
        case 3: return g_y2;
        case 4: return g_p2;
        case 5: return g_tx2;
        case 6: return g_y3;
        case 7: return g_tB1;
        case 8: return g_tB2;
        case 9: return g_tB3;
    }
    return nullptr;
}

__device__ __forceinline__ unsigned f2tf(float x) {
    unsigned u;
    asm("cvt.rna.tf32.f32 %0, %1;" : "=r"(u) : "f"(x));
    return u;
}
__device__ __forceinline__ unsigned fui(float x) { return __float_as_uint(x); }

// ---------------- fused prep: init graph/sums + tf32 pre-convert all weights ----------------
#define B1E (768 * 512)
#define B2E (1024 * 256)
#define B3E (768 * 128)
#define PREPE (B1E + B2E + B3E)
__global__ void k_prep(const float* __restrict__ W1_0,
                       const float* __restrict__ W2_0, const float* __restrict__ W2_1,
                       const float* __restrict__ W3_0, const float* __restrict__ W3_1,
                       const float* __restrict__ W3_2) {
    int idx = blockIdx.x * blockDim.x + threadIdx.x;
    if (idx < NN) { g_deg[idx] = 0.0f; g_cnt[idx] = 0; }
    if (idx < 896) { g_sums[idx] = 0.0f; g_ssqs[idx] = 0.0f; }
    if (idx < B1E) {
        g_tB1[idx] = __uint_as_float(f2tf(W1_0[idx]));
    } else if (idx < B1E + B2E) {
        int i2 = idx - B1E;
        int row = i2 >> 8;
        int col = i2 & 255;
        const float* B = (row < 512) ? W2_0 : W2_1;
        g_tB2[i2] = __uint_as_float(f2tf(B[(row & 511) * 256 + col]));
    } else if (idx < PREPE) {
        int i3 = idx - B1E - B2E;
        int row = i3 >> 7;
        int col = i3 & 127;
        int seg = row >> 8;
        const float* B = (seg == 0) ? W3_0 : (seg == 1) ? W3_1 : W3_2;
        g_tB3[i3] = __uint_as_float(f2tf(B[(row & 255) * 128 + col]));
    }
}

// ---------------- graph build (ELL by dst) ----------------
__global__ void k_deg(const int* __restrict__ ei, const float* __restrict__ ea) {
    int e = blockIdx.x * blockDim.x + threadIdx.x;
    if (e >= EE) return;
    atomicAdd(&g_deg[ei[e]], ea[e]);
}
__global__ void k_norm_push(const int* __restrict__ ei, const float* __restrict__ ea) {
    int e = blockIdx.x * blockDim.x + threadIdx.x;
    if (e >= EE) return;
    int s = ei[e];
    int d = ei[EE + e];
    float ds = g_deg[s], dd = g_deg[d];
    float is = (ds > 0.0f) ? rsqrtf(ds) : 0.0f;
    float id = (dd > 0.0f) ? rsqrtf(dd) : 0.0f;
    float w = -is * ea[e] * id;
    int pos = atomicAdd(&g_cnt[d], 1);
    g_ell_src[d * ELLW + pos] = s;
    g_ell_w[d * ELLW + pos] = w;
}

// ---------------- tf32 GEMM (R13-exact): BM=64, BN=128, BKT=16; fragment-major A smem,
// padded scalar-B smem, preconverted B, pointer-walk loop ----------------
#define BMT 64
#define BNT 128
#define BKT 16
#define NF 4
#define A_STAGE (2 * NF * 128)
#define BPAD 136

__global__ __launch_bounds__(256, 3) void gemm_tf32(
    const float* __restrict__ Aext, int aid0, int aid1, int aid2, int tBid,
    const float* __restrict__ bias, int Cid,
    int M, int N, int Kseg, int segs, int soff, int coff0)
{
    __shared__ __align__(16) float As[2][A_STAGE];
    __shared__ __align__(16) float Bs[2][BKT][BPAD];

    const float* Ap[3];
    Ap[0] = Aext ? Aext : buf(aid0);
    Ap[1] = buf(aid1);
    Ap[2] = buf(aid2);
    float* C = buf(Cid);

    const int tid = threadIdx.x;
    const int lane = tid & 31;
    const int warp = tid >> 5;
    const int qr = lane >> 2;
    const int qc = lane & 3;
    const int wm = (warp & 1) * 32;
    const int ms0 = (warp & 1) * 2;
    const int wn = (warp >> 1) * 32;

    const int row0 = blockIdx.y * BMT;
    const int col0 = blockIdx.x * BNT;

    const int arow = tid >> 2;
    const int ak = (tid & 3) << 2;
    const bool avalid = (row0 + arow) < M;
    const int wr = arow & 15;
    const int wms = arow >> 4;
    const int wkh = ak >> 3;
    const int wkb = (ak >> 2) & 1;
    const int xsw = ((wr >> 1) & 3) << 2;
    const int awbase = (wkh * NF + wms) * 128 + ((wr & 7) << 4) + (wr >> 3) + (wkb << 1);

    const int rpos = (qr << 2) + (qc ^ ((qr >> 1) & 3));
    const int ardbase = ms0 * 128 + (rpos << 2);

    const int brow = tid >> 5;
    const int bcol = (tid & 31) << 2;

    float acc[2][4][4];
#pragma unroll
    for (int i = 0; i < 2; i++)
#pragma unroll
        for (int j = 0; j < 4; j++)
#pragma unroll
            for (int e = 0; e < 4; e++) acc[i][j][e] = 0.0f;

    const size_t aoff = (size_t)(row0 + arow) * Kseg + ak;
    const float* pA = Ap[0] + aoff;
    const float* psc = g_bnsc + (coff0 >= 0 ? coff0 : 0) + ak;
    const float* psh = g_bnsh + (coff0 >= 0 ? coff0 : 0) + ak;
    const float* pB = buf(tBid) + (size_t)brow * N + col0 + bcol;
    const int bstep = BKT * N;
    int segi = 0, kcnt = 0;
    const int kperseg = Kseg / BKT;
    const int niter = kperseg * segs;

    float4 rA, rB[2];
    auto fetch = [&]() {
        rA = make_float4(0.f, 0.f, 0.f, 0.f);
        if (avalid) rA = *(const float4*)pA;
        if (coff0 >= 0 && segi == 0) {
            float4 sc = *(const float4*)psc;
            float4 sh = *(const float4*)psh;
            rA.x = fmaxf(fmaf(rA.x, sc.x, sh.x), 0.f);
            rA.y = fmaxf(fmaf(rA.y, sc.y, sh.y), 0.f);
            rA.z = fmaxf(fmaf(rA.z, sc.z, sh.z), 0.f);
            rA.w = fmaxf(fmaf(rA.w, sc.w, sh.w), 0.f);
        }
        rB[0] = *(const float4*)pB;
        rB[1] = *(const float4*)(pB + (size_t)8 * N);
    };
    auto advance = [&]() {
        kcnt++;
        if (kcnt == kperseg) {
            kcnt = 0; segi++;
            if (segi < segs) pA = Ap[segi] + aoff;
        } else {
            pA += BKT;
        }
        psc += BKT; psh += BKT;
        pB += bstep;
    };
    auto commit = [&](int s) {
        float* Aw = As[s];
        Aw[awbase + ((0 << 2) ^ xsw)] = __uint_as_float(f2tf(rA.x));
        Aw[awbase + ((1 << 2) ^ xsw)] = __uint_as_float(f2tf(rA.y));
        Aw[awbase + ((2 << 2) ^ xsw)] = __uint_as_float(f2tf(rA.z));
        Aw[awbase + ((3 << 2) ^ xsw)] = __uint_as_float(f2tf(rA.w));
        *(float4*)&Bs[s][brow][bcol] = rB[0];
        *(float4*)&Bs[s][brow + 8][bcol] = rB[1];
    };

    fetch();
    advance();
    commit(0);
    __syncthreads();

    int cur = 0;
    for (int it = 0; it < niter; it++, cur ^= 1) {
        const bool hasNext = (it + 1) < niter;
        if (hasNext) { fetch(); advance(); }

        const float* Ac = As[cur];
        const float* Bc = &Bs[cur][0][0];
#pragma unroll
        for (int kh = 0; kh < 2; kh++) {
            const float* Af = Ac + kh * (NF * 128) + ardbase;
            float4 fa0 = *(const float4*)(Af);
            float4 fa1 = *(const float4*)(Af + 128);
            const float* Bk0 = Bc + (kh * 8 + qc) * BPAD + wn + qr;
            const float* Bk1 = Bk0 + 4 * BPAD;
#pragma unroll
            for (int j = 0; j < 4; j++) {
                unsigned b0 = fui(Bk0[8 * j]);
                unsigned b1 = fui(Bk1[8 * j]);
                asm volatile(
                    "mma.sync.aligned.m16n8k8.row.col.f32.tf32.tf32.f32 "
                    "{%0,%1,%2,%3}, {%4,%5,%6,%7}, {%8,%9}, {%0,%1,%2,%3};"
                    : "+f"(acc[0][j][0]), "+f"(acc[0][j][1]),
                      "+f"(acc[0][j][2]), "+f"(acc[0][j][3])
                    : "r"(fui(fa0.x)), "r"(fui(fa0.y)), "r"(fui(fa0.z)), "r"(fui(fa0.w)),
                      "r"(b0), "r"(b1));
                asm volatile(
                    "mma.sync.aligned.m16n8k8.row.col.f32.tf32.tf32.f32 "
                    "{%0,%1,%2,%3}, {%4,%5,%6,%7}, {%8,%9}, {%0,%1,%2,%3};"
                    : "+f"(acc[1][j][0]), "+f"(acc[1][j][1]),
                      "+f"(acc[1][j][2]), "+f"(acc[1][j][3])
                    : "r"(fui(fa1.x)), "r"(fui(fa1.y)), "r"(fui(fa1.z)), "r"(fui(fa1.w)),
                      "r"(b0), "r"(b1));
            }
        }

        if (hasNext) commit(cur ^ 1);
        __syncthreads();
    }

    // ---- epilogue: bias add, store raw, fused BN stats ----
#pragma unroll
    for (int j = 0; j < 4; j++) {
        int c = col0 + wn + 8 * j + 2 * qc;
        float bx = bias[c], by = bias[c + 1];
#pragma unroll
        for (int i = 0; i < 2; i++) {
            acc[i][j][0] += bx; acc[i][j][1] += by;
            acc[i][j][2] += bx; acc[i][j][3] += by;
        }
    }
#pragma unroll
    for (int i = 0; i < 2; i++) {
        int r = row0 + wm + 16 * i + qr;
#pragma unroll
        for (int j = 0; j < 4; j++) {
            int c = col0 + wn + 8 * j + 2 * qc;
            if (r < M)
                *(float2*)(C + (size_t)r * N + c) = make_float2(acc[i][j][0], acc[i][j][1]);
            if (r + 8 < M)
                *(float2*)(C + (size_t)(r + 8) * N + c) = make_float2(acc[i][j][2], acc[i][j][3]);
        }
    }
#pragma unroll
    for (int j = 0; j < 4; j++) {
        float s0 = 0.f, q0 = 0.f, s1 = 0.f, q1 = 0.f;
#pragma unroll
        for (int i = 0; i < 2; i++) {
            int r = row0 + wm + 16 * i + qr;
            if (r < M) {
                s0 += acc[i][j][0]; q0 += acc[i][j][0] * acc[i][j][0];
                s1 += acc[i][j][1]; q1 += acc[i][j][1] * acc[i][j][1];
            }
            if (r + 8 < M) {
                s0 += acc[i][j][2]; q0 += acc[i][j][2] * acc[i][j][2];
                s1 += acc[i][j][3]; q1 += acc[i][j][3] * acc[i][j][3];
            }
        }
#pragma unroll
        for (int off = 4; off < 32; off <<= 1) {
            s0 += __shfl_xor_sync(0xffffffff, s0, off);
            q0 += __shfl_xor_sync(0xffffffff, q0, off);
            s1 += __shfl_xor_sync(0xffffffff, s1, off);
            q1 += __shfl_xor_sync(0xffffffff, q1, off);
        }
        if (qr == 0) {
            int c = col0 + wn + 8 * j + 2 * qc;
            atomicAdd(&g_sums[soff + c], s0);
            atomicAdd(&g_ssqs[soff + c], q0);
            atomicAdd(&g_sums[soff + c + 1], s1);
            atomicAdd(&g_ssqs[soff + c + 1], q1);
        }
    }
}

// ---------------- propagation (ELL by dst; BN coefs computed inline, block0 stores them) ----------------
__global__ void k_prop(int hid, int outid, int F, int coff,
                       const float* __restrict__ gamma, const float* __restrict__ beta) {
    const float* h = buf(hid);
    float* out = buf(outid);
    int node = blockIdx.x;
    int t = threadIdx.x;
    int cnt = g_cnt[node];
    int base = node * ELLW;
    const float inv_n = 1.0f / (float)NN;
    int c0 = t * 4;
    float4 gm = *(const float4*)(gamma + c0);
    float4 bt = *(const float4*)(beta + c0);
    float4 sc, sh;
    {
        float mu, var;
        mu = g_sums[coff + c0 + 0] * inv_n;
        var = g_ssqs[coff + c0 + 0] * inv_n - mu * mu;
        sc.x = gm.x * rsqrtf(var + EPS); sh.x = bt.x - mu * sc.x;
        mu = g_sums[coff + c0 + 1] * inv_n;
        var = g_ssqs[coff + c0 + 1] * inv_n - mu * mu;
        sc.y = gm.y * rsqrtf(var + EPS); sh.y = bt.y - mu * sc.y;
        mu = g_sums[coff + c0 + 2] * inv_n;
        var = g_ssqs[coff + c0 + 2] * inv_n - mu * mu;
        sc.z = gm.z * rsqrtf(var + EPS); sh.z = bt.z - mu * sc.z;
        mu = g_sums[coff + c0 + 3] * inv_n;
        var = g_ssqs[coff + c0 + 3] * inv_n - mu * mu;
        sc.w = gm.w * rsqrtf(var + EPS); sh.w = bt.w - mu * sc.w;
    }
    if (node == 0) {
        *(float4*)(g_bnsc + coff + c0) = sc;
        *(float4*)(g_bnsh + coff + c0) = sh;
    }
    float4 acc = make_float4(0.f, 0.f, 0.f, 0.f);
    for (int e = 0; e < cnt; e++) {
        int s = g_ell_src[base + e];
        float w = g_ell_w[base + e];
        float4 v = *(const float4*)(h + (size_t)s * F + c0);
        v.x = fmaxf(fmaf(v.x, sc.x, sh.x), 0.f);
        v.y = fmaxf(fmaf(v.y, sc.y, sh.y), 0.f);
        v.z = fmaxf(fmaf(v.z, sc.z, sh.z), 0.f);
        v.w = fmaxf(fmaf(v.w, sc.w, sh.w), 0.f);
        acc.x += w * v.x; acc.y += w * v.y; acc.z += w * v.z; acc.w += w * v.w;
    }
    *(float4*)(out + (size_t)node * F + c0) = acc;
}

__global__ void k_prop_cheb(int hid, int subid, int outid, int F, int subcoff) {
    const float* h = buf(hid);
    const float* sub = buf(subid);
    float* out = buf(outid);
    int node = blockIdx.x;
    int t = threadIdx.x;
    int cnt = g_cnt[node];
    int base = node * ELLW;
    float4 acc = make_float4(0.f, 0.f, 0.f, 0.f);
    for (int e = 0; e < cnt; e++) {
        int s = g_ell_src[base + e];
        float w = g_ell_w[base + e];
        float4 v = *(const float4*)(h + (size_t)s * F + t * 4);
        acc.x += w * v.x; acc.y += w * v.y; acc.z += w * v.z; acc.w += w * v.w;
    }
    float4 sc = *(const float4*)(g_bnsc + subcoff + t * 4);
    float4 sh = *(const float4*)(g_bnsh + subcoff + t * 4);
    float4 sv = *(const float4*)(sub + (size_t)node * F + t * 4);
    sv.x = fmaxf(fmaf(sv.x, sc.x, sh.x), 0.f);
    sv.y = fmaxf(fmaf(sv.y, sc.y, sh.y), 0.f);
    sv.z = fmaxf(fmaf(sv.z, sc.z, sh.z), 0.f);
    sv.w = fmaxf(fmaf(sv.w, sc.w, sh.w), 0.f);
    float4 r;
    r.x = 2.0f * acc.x - sv.x;
    r.y = 2.0f * acc.y - sv.y;
    r.z = 2.0f * acc.z - sv.z;
    r.w = 2.0f * acc.w - sv.w;
    *(float4*)(out + (size_t)node * F + t * 4) = r;
}

// ---------------- fc (bn3 coefs computed inline; 128 -> 6) + log_softmax ----------------
__global__ void k_fc(const float* __restrict__ W, const float* __restrict__ bias,
                     const float* __restrict__ gamma3, const float* __restrict__ beta3,
                     float* __restrict__ out, int n) {
    const float* h = g_y3;
    int gtid = blockIdx.x * blockDim.x + threadIdx.x;
    int node = gtid >> 5;
    int lane = gtid & 31;
    if (node >= n) return;
    const float inv_n = 1.0f / (float)n;
    float hv[4];
#pragma unroll
    for (int k = 0; k < 4; k++) {
        int col = lane + 32 * k;
        float mu = g_sums[768 + col] * inv_n;
        float var = g_ssqs[768 + col] * inv_n - mu * mu;
        float sc = gamma3[col] * rsqrtf(var + EPS);
        float shv = beta3[col] - mu * sc;
        float raw = h[(size_t)node * 128 + col];
        hv[k] = fmaf(raw, sc, shv);
    }
    float logit[6];
#pragma unroll
    for (int j = 0; j < 6; j++) {
        float s = 0.0f;
#pragma unroll
        for (int k = 0; k < 4; k++) s += hv[k] * W[(lane + 32 * k) * 6 + j];
#pragma unroll
        for (int o = 16; o > 0; o >>= 1) s += __shfl_xor_sync(0xffffffff, s, o);
        logit[j] = s + bias[j];
    }
    if (lane == 0) {
        float mx = logit[0];
#pragma unroll
        for (int j = 1; j < 6; j++) mx = fmaxf(mx, logit[j]);
        float se = 0.0f;
#pragma unroll
        for (int j = 0; j < 6; j++) se += expf(logit[j] - mx);
        float lse = mx + logf(se);
#pragma unroll
        for (int j = 0; j < 6; j++) out[(size_t)node * 6 + j] = logit[j] - lse;
    }
}

// ---------------- launch ----------------
extern "C" void kernel_launch(void* const* d_in, const int* in_sizes, int n_in,
                              void* d_out, int out_size) {
    const float* x    = (const float*)d_in[0];
    const int*   ei   = (const int*)d_in[1];
    const float* ea   = (const float*)d_in[2];
    const float* W1_0 = (const float*)d_in[3];
    const float* b1   = (const float*)d_in[4];
    const float* g1   = (const float*)d_in[5];
    const float* be1  = (const float*)d_in[6];
    const float* W2_0 = (const float*)d_in[7];
    const float* W2_1 = (const float*)d_in[8];
    const float* b2   = (const float*)d_in[9];
    const float* g2   = (const float*)d_in[10];
    const float* be2  = (const float*)d_in[11];
    const float* W3_0 = (const float*)d_in[12];
    const float* W3_1 = (const float*)d_in[13];
    const float* W3_2 = (const float*)d_in[14];
    const float* b3   = (const float*)d_in[15];
    const float* g3   = (const float*)d_in[16];
    const float* be3  = (const float*)d_in[17];
    const float* fcW  = (const float*)d_in[18];
    const float* fcb  = (const float*)d_in[19];
    float* out = (float*)d_out;

    // one-time stream/event setup (host objects; created outside capture on first call)
    static cudaStream_t s1 = nullptr;
    static cudaEvent_t evFork = nullptr, evJoin = nullptr;
    if (s1 == nullptr) {
        cudaStreamCreateWithFlags(&s1, cudaStreamNonBlocking);
        cudaEventCreateWithFlags(&evFork, cudaEventDisableTiming);
        cudaEventCreateWithFlags(&evJoin, cudaEventDisableTiming);
    }

    // ---- fused prep: init + weight tf32 pre-convert ----
    k_prep<<<CEILDIV(PREPE, 256), 256>>>(W1_0, W2_0, W2_1, W3_0, W3_1, W3_2);

    // ---- fork: graph build on side stream, overlapped with gemm1 ----
    cudaEventRecord(evFork, 0);
    cudaStreamWaitEvent(s1, evFork, 0);
    k_deg<<<CEILDIV(EE, 256), 256, 0, s1>>>(ei, ea);
    k_norm_push<<<CEILDIV(EE, 256), 256, 0, s1>>>(ei, ea);
    cudaEventRecord(evJoin, s1);

    const int GY = CEILDIV(NN, BMT);   // 157

    // ---- layer 1 (main stream, parallel with build) ----
    gemm_tf32<<<dim3(512 / BNT, GY), 256>>>(
        x, 0, 0, 0, 7, b1, 1, NN, 512, 768, 1, 0, -1);

    // ---- join: prop needs graph + y1 + sums ----
    cudaStreamWaitEvent(0, evJoin, 0);

    // ---- layer 2 ----
    k_prop<<<NN, 128>>>(1, 2, 512, 0, g1, be1);
    gemm_tf32<<<dim3(256 / BNT, GY), 256>>>(
        nullptr, 1, 2, 0, 8, b2, 3, NN, 256, 512, 2, 512, 0);

    // ---- layer 3 ----
    k_prop<<<NN, 64>>>(3, 4, 256, 512, g2, be2);
    k_prop_cheb<<<NN, 64>>>(4, 3, 5, 256, 512);
    gemm_tf32<<<dim3(128 / BNT, GY), 256>>>(
        nullptr, 3, 4, 5, 9, b3, 6, NN, 128, 256, 3, 768, 512);

    // ---- fc (bn3 coefs inline) + log_softmax ----
    k_fc<<<CEILDIV(NN * 32, 256), 256>>>(fcW, fcb, g3, be3, out, NN);
}